// round 5
// baseline (speedup 1.0000x reference)
#include <cuda_runtime.h>
#include <cstdint>
#include <cstddef>

#define NNODES 8192
#define DDIM   16
#define BATCH  4
#define NC     64                       // B*D output columns
#define MT     128                      // M tile rows
#define KT     32                       // K per stage
#define SPLITS 4
#define KRANGE (NNODES / SPLITS)        // 2048
#define NIT    (KRANGE / KT)            // 64
#define NMT    (NNODES / MT)            // 64
#define STAGES 4

#define AROWF  36                       // fp32 words per A smem row (32 data + 4 pad)
#define AROWB  144
#define XROWB  48                       // bytes per X smem row (32 data + 16 pad)
#define A_BYTES (MT * AROWB)            // 18432
#define X_BYTES (NC * XROWB)            // 3072
#define STAGE_BYTES (A_BYTES + X_BYTES) // 21504
#define SMEM_TOTAL  (STAGES * STAGE_BYTES) // 86016

#define QS 2080768.0f                   // 254 * 8192 (A quant scale)

__device__ __align__(128) int8_t g_X8[NC * NNODES];            // 512 KB
__device__ __align__(16)  float  g_sx[NC];
__device__ __align__(16)  int    g_qsum[NC * SPLITS];
__device__ __align__(128) float  g_part[SPLITS * NNODES * NC]; // 8 MB

// ---- helpers ----
__device__ __forceinline__ uint32_t smem_u32(const void* p) {
    uint32_t a;
    asm("{ .reg .u64 t; cvta.to.shared.u64 t, %1; cvt.u32.u64 %0, t; }" : "=r"(a) : "l"(p));
    return a;
}
__device__ __forceinline__ void cp_async16(uint32_t smem_dst, const void* gmem_src) {
    asm volatile("cp.async.cg.shared.global [%0], [%1], 16;" :: "r"(smem_dst), "l"(gmem_src));
}
#define CP_COMMIT() asm volatile("cp.async.commit_group;" ::: "memory")

__device__ __forceinline__ uint32_t pack_s8x4(int q0, int q1, int q2, int q3) {
    uint32_t z = 0, lo, r;
    asm("cvt.pack.sat.s8.s32.b32 %0, %1, %2, %3;" : "=r"(lo) : "r"(q3), "r"(q2), "r"(z));
    asm("cvt.pack.sat.s8.s32.b32 %0, %1, %2, %3;" : "=r"(r) : "r"(q1), "r"(q0), "r"(lo));
    return r;   // byte0=q0 .. byte3=q3
}

// quantize 4 consecutive fp32 A values: q = rn(a*QS - 127), a in [0, 1/8192)
__device__ __forceinline__ uint32_t quantA4(float4 f) {
    int q0 = __float2int_rn(fmaf(f.x, QS, -127.0f));
    int q1 = __float2int_rn(fmaf(f.y, QS, -127.0f));
    int q2 = __float2int_rn(fmaf(f.z, QS, -127.0f));
    int q3 = __float2int_rn(fmaf(f.w, QS, -127.0f));
    return pack_s8x4(q0, q1, q2, q3);
}

__device__ __forceinline__ void mma_s8(int* c, const uint32_t* a, const uint32_t* b) {
    asm volatile(
        "mma.sync.aligned.m16n8k32.row.col.s32.s8.s8.s32 "
        "{%0,%1,%2,%3}, {%4,%5,%6,%7}, {%8,%9}, {%0,%1,%2,%3};"
        : "+r"(c[0]), "+r"(c[1]), "+r"(c[2]), "+r"(c[3])
        : "r"(a[0]), "r"(a[1]), "r"(a[2]), "r"(a[3]), "r"(b[0]), "r"(b[1]));
}

// ---------------- kernel 1: per-column int8 quantization of X ----------------
// column c = b*16+d holds h[b][m*16+d] over m; exact per-column maxabs scale,
// plus per-(column, K-split) sums of q for the A-offset correction.
__global__ void __launch_bounds__(256) quantx_kernel(const float* __restrict__ h) {
    __shared__ float smax[256];
    __shared__ int   ssum[4];
    int c = blockIdx.x;
    int b = c >> 4, d = c & 15;
    int t = threadIdx.x;
    const float* src = h + (size_t)b * (NNODES * DDIM) + d;

    float v[32];
    float mx = 0.0f;
#pragma unroll
    for (int i = 0; i < 32; i++) {
        v[i] = src[(size_t)(t * 32 + i) * DDIM];
        mx = fmaxf(mx, fabsf(v[i]));
    }
    smax[t] = mx;
    __syncthreads();
    for (int s = 128; s > 0; s >>= 1) {
        if (t < s) smax[t] = fmaxf(smax[t], smax[t + s]);
        __syncthreads();
    }
    mx = smax[0];
    float sx  = mx / 127.0f + 1e-30f;
    float inv = 1.0f / sx;
    if (t < 4) ssum[t] = 0;
    __syncthreads();

    int sum = 0;
    uint32_t* dst = (uint32_t*)(g_X8 + (size_t)c * NNODES + t * 32);
#pragma unroll
    for (int i = 0; i < 8; i++) {
        int q0 = __float2int_rn(v[4 * i + 0] * inv);
        int q1 = __float2int_rn(v[4 * i + 1] * inv);
        int q2 = __float2int_rn(v[4 * i + 2] * inv);
        int q3 = __float2int_rn(v[4 * i + 3] * inv);
        sum += q0 + q1 + q2 + q3;
        dst[i] = pack_s8x4(q0, q1, q2, q3);
    }
    atomicAdd(&ssum[t >> 6], sum);   // thread's 32 k all lie in split t>>6
    __syncthreads();
    if (t == 0) g_sx[c] = sx;
    if (t < 4) g_qsum[c * 4 + t] = ssum[t];
}

// ---------------- kernel 2: int8 mma.sync GEMM -> g_part ----------------
// C[m][c] = sum_k A[m][k]*X[c][k]; A quantized in registers from fp32 smem.
__global__ void __launch_bounds__(256, 2) gemm_kernel(const float* __restrict__ A) {
    extern __shared__ char smem[];
    uint32_t sb = smem_u32(smem);

    int tid   = threadIdx.x;
    int n0    = blockIdx.x * MT;
    int split = blockIdx.y;
    int kbase = split * KRANGE;

    int lane = tid & 31, wid = tid >> 5;
    int wm = wid & 3, wn = wid >> 2;
    int qrow = lane >> 2, qcol = lane & 3;

    // cp.async coords: A = 1024 16B chunks (128 rows x 8); X = 128 chunks (64 rows x 2)
    uint32_t offA[4]; size_t gofA[4];
#pragma unroll
    for (int i = 0; i < 4; i++) {
        int q = i * 256 + tid;
        int row = q >> 3, c16 = q & 7;
        offA[i] = (uint32_t)(row * AROWB + c16 * 16);
        gofA[i] = (size_t)(n0 + row) * NNODES + (size_t)c16 * 4;   // fp32 elems
    }
    bool doX = tid < 128;
    uint32_t offX = 0; size_t gofX = 0;
    {
        int row = tid >> 1, c16 = tid & 1;
        offX = (uint32_t)(row * XROWB + c16 * 16);
        gofX = (size_t)row * NNODES + (size_t)c16 * 16;            // bytes
    }

    // prologue: tiles 0..2 -> slots 0..2
#pragma unroll
    for (int s = 0; s < STAGES - 1; s++) {
        int k0 = kbase + s * KT;
        uint32_t ab = sb + s * STAGE_BYTES;
#pragma unroll
        for (int i = 0; i < 4; i++) cp_async16(ab + offA[i], A + gofA[i] + k0);
        if (doX) cp_async16(ab + A_BYTES + offX, g_X8 + gofX + k0);
        CP_COMMIT();
    }

    int acc[2][4][4];
#pragma unroll
    for (int mf = 0; mf < 2; mf++)
#pragma unroll
        for (int nf = 0; nf < 4; nf++)
#pragma unroll
            for (int r = 0; r < 4; r++) acc[mf][nf][r] = 0;

    const int arow0 = wm * 32 + qrow;
    const int bcol0 = wn * 32 + qrow;

    for (int it = 0; it < NIT; it++) {
        int slot = it & (STAGES - 1);
        asm volatile("cp.async.wait_group %0;" :: "n"(STAGES - 2) : "memory");
        __syncthreads();

        // refill freed slot first (hide latency)
        int nt = it + STAGES - 1;
        if (nt < NIT) {
            int k0 = kbase + nt * KT;
            uint32_t ab = sb + (nt & (STAGES - 1)) * STAGE_BYTES;
#pragma unroll
            for (int i = 0; i < 4; i++) cp_async16(ab + offA[i], A + gofA[i] + k0);
            if (doX) cp_async16(ab + A_BYTES + offX, g_X8 + gofX + k0);
        }
        CP_COMMIT();

        const float* As = (const float*)(smem + slot * STAGE_BYTES);
        const char*  Xs = smem + slot * STAGE_BYTES + A_BYTES;

        uint32_t a[2][4];
#pragma unroll
        for (int mf = 0; mf < 2; mf++) {
            int r = arow0 + mf * 16;
            float4 f0 = *(const float4*)(As + (size_t)r * AROWF + 4 * qcol);
            float4 f1 = *(const float4*)(As + (size_t)(r + 8) * AROWF + 4 * qcol);
            float4 f2 = *(const float4*)(As + (size_t)r * AROWF + 4 * qcol + 16);
            float4 f3 = *(const float4*)(As + (size_t)(r + 8) * AROWF + 4 * qcol + 16);
            a[mf][0] = quantA4(f0);
            a[mf][1] = quantA4(f1);
            a[mf][2] = quantA4(f2);
            a[mf][3] = quantA4(f3);
        }
        uint32_t bf[4][2];
#pragma unroll
        for (int nf = 0; nf < 4; nf++) {
            int c = bcol0 + nf * 8;
            bf[nf][0] = *(const uint32_t*)(Xs + c * XROWB + 4 * qcol);
            bf[nf][1] = *(const uint32_t*)(Xs + c * XROWB + 4 * qcol + 16);
        }
#pragma unroll
        for (int mf = 0; mf < 2; mf++)
#pragma unroll
            for (int nf = 0; nf < 4; nf++)
                mma_s8(acc[mf][nf], a[mf], bf[nf]);
    }
    asm volatile("cp.async.wait_group 0;" ::: "memory");

    // epilogue: hg_part = sx_c/QS * (S32 + 127*qsum_c_split)
    const float invS = 1.0f / QS;
#pragma unroll
    for (int nf = 0; nf < 4; nf++) {
        int c0 = wn * 32 + nf * 8 + 2 * qcol;
        float sc0 = g_sx[c0] * invS;
        float sc1 = g_sx[c0 + 1] * invS;
        int qs0 = 127 * g_qsum[c0 * 4 + split];
        int qs1 = 127 * g_qsum[(c0 + 1) * 4 + split];
#pragma unroll
        for (int mf = 0; mf < 2; mf++) {
            int m = n0 + wm * 32 + mf * 16 + qrow;
            float v0 = (float)(acc[mf][nf][0] + qs0) * sc0;
            float v1 = (float)(acc[mf][nf][1] + qs1) * sc1;
            *(float2*)(g_part + ((size_t)split * NNODES + m) * NC + c0) = make_float2(v0, v1);
            float v2 = (float)(acc[mf][nf][2] + qs0) * sc0;
            float v3 = (float)(acc[mf][nf][3] + qs1) * sc1;
            *(float2*)(g_part + ((size_t)split * NNODES + m + 8) * NC + c0) = make_float2(v2, v3);
        }
    }
}

// ---------------- kernel 3: fused MLPs ----------------
__global__ void __launch_bounds__(256) mlp_kernel(
    const float* __restrict__ h, const float* __restrict__ t,
    const float* __restrict__ W1f, const float* __restrict__ b1f,
    const float* __restrict__ W2f, const float* __restrict__ b2f,
    const float* __restrict__ W1g, const float* __restrict__ b1g,
    const float* __restrict__ W2g, const float* __restrict__ b2g,
    float* __restrict__ out) {
    __shared__ float sW1f[17 * 64], sW2f[64 * 16], sW1g[17 * 64], sW2g[64 * 16];
    __shared__ float sb1f[64], sb1g[64], sb2f[16], sb2g[16];
    int tid = threadIdx.x;
    for (int i = tid; i < 17 * 64; i += 256) { sW1f[i] = W1f[i]; sW1g[i] = W1g[i]; }
    for (int i = tid; i < 64 * 16; i += 256) { sW2f[i] = W2f[i]; sW2g[i] = W2g[i]; }
    if (tid < 64) { sb1f[tid] = b1f[tid]; sb1g[tid] = b1g[tid]; }
    if (tid < 16) { sb2f[tid] = b2f[tid]; sb2g[tid] = b2g[tid]; }
    __syncthreads();

    float tv = t[0];
    int gid = blockIdx.x * 256 + tid;
    int b = gid >> 13, n = gid & (NNODES - 1);

    float x[16], y[16];
    {
        size_t base = (size_t)n * NC + (size_t)b * DDIM;
        const float4* p0 = (const float4*)(g_part + base);
        const float4* p1 = (const float4*)(g_part + (size_t)1 * NNODES * NC + base);
        const float4* p2 = (const float4*)(g_part + (size_t)2 * NNODES * NC + base);
        const float4* p3 = (const float4*)(g_part + (size_t)3 * NNODES * NC + base);
#pragma unroll
        for (int k = 0; k < 4; k++) {
            float4 a = p0[k], bb = p1[k], c = p2[k], d = p3[k];
            x[4 * k + 0] = a.x + bb.x + c.x + d.x;
            x[4 * k + 1] = a.y + bb.y + c.y + d.y;
            x[4 * k + 2] = a.z + bb.z + c.z + d.z;
            x[4 * k + 3] = a.w + bb.w + c.w + d.w;
        }
        const float4* ph = (const float4*)(h + (size_t)b * NNODES * DDIM + (size_t)n * DDIM);
#pragma unroll
        for (int k = 0; k < 4; k++) {
            float4 a = ph[k];
            y[4 * k + 0] = a.x; y[4 * k + 1] = a.y; y[4 * k + 2] = a.z; y[4 * k + 3] = a.w;
        }
    }

    float drift[16], dacc[16];
#pragma unroll
    for (int d = 0; d < 16; d++) { drift[d] = sb2f[d]; dacc[d] = sb2g[d]; }

    for (int j = 0; j < 64; j++) {
        float zf = sb1f[j] + tv * sW1f[16 * 64 + j];
        float zg = sb1g[j] + tv * sW1g[16 * 64 + j];
#pragma unroll
        for (int i = 0; i < 16; i++) {
            zf = fmaf(x[i], sW1f[i * 64 + j], zf);
            zg = fmaf(y[i], sW1g[i * 64 + j], zg);
        }
        float af = 1.0f - 2.0f / (__expf(2.0f * zf) + 1.0f);   // tanh via MUFU exp
        float ag = 1.0f / (1.0f + __expf(-zg));
#pragma unroll
        for (int d = 0; d < 16; d++) {
            drift[d] = fmaf(af, sW2f[j * 16 + d], drift[d]);
            dacc[d]  = fmaf(ag, sW2g[j * 16 + d], dacc[d]);
        }
    }

    size_t o0 = (size_t)b * NNODES * DDIM + (size_t)n * DDIM;
    float4* od = (float4*)(out + o0);
    float4* og = (float4*)(out + (size_t)BATCH * NNODES * DDIM + o0);
#pragma unroll
    for (int k = 0; k < 4; k++) {
        od[k] = make_float4(drift[4 * k], drift[4 * k + 1], drift[4 * k + 2], drift[4 * k + 3]);
        float g0 = 0.1f / (1.0f + __expf(-dacc[4 * k + 0]));
        float g1 = 0.1f / (1.0f + __expf(-dacc[4 * k + 1]));
        float g2 = 0.1f / (1.0f + __expf(-dacc[4 * k + 2]));
        float g3 = 0.1f / (1.0f + __expf(-dacc[4 * k + 3]));
        og[k] = make_float4(g0, g1, g2, g3);
    }
}

extern "C" void kernel_launch(void* const* d_in, const int* in_sizes, int n_in,
                              void* d_out, int out_size) {
    (void)in_sizes; (void)n_in; (void)out_size;
    const float* h   = (const float*)d_in[0];
    const float* t   = (const float*)d_in[1];
    const float* A   = (const float*)d_in[2];
    const float* W1f = (const float*)d_in[3];
    const float* b1f = (const float*)d_in[4];
    const float* W2f = (const float*)d_in[5];
    const float* b2f = (const float*)d_in[6];
    const float* W1g = (const float*)d_in[7];
    const float* b1g = (const float*)d_in[8];
    const float* W2g = (const float*)d_in[9];
    const float* b2g = (const float*)d_in[10];
    float* out = (float*)d_out;

    cudaFuncSetAttribute(gemm_kernel, cudaFuncAttributeMaxDynamicSharedMemorySize, SMEM_TOTAL);

    quantx_kernel<<<64, 256>>>(h);
    gemm_kernel<<<dim3(NMT, SPLITS), 256, SMEM_TOTAL>>>(A);
    mlp_kernel<<<128, 256>>>(h, t, W1f, b1f, W2f, b2f, W1g, b1g, W2g, b2g, out);
}

// round 6
// speedup vs baseline: 1.3859x; 1.3859x over previous
#include <cuda_runtime.h>
#include <cuda_fp16.h>
#include <cstdint>
#include <cstddef>

#define NNODES 8192
#define DDIM   16
#define BATCH  4
#define NC     64                       // B*D output columns
#define MT     128                      // M tile
#define KT     32                       // K per stage
#define SPLITS 4
#define KRANGE (NNODES / SPLITS)        // 2048
#define NIT    (KRANGE / KT)            // 64
#define NMT    (NNODES / MT)            // 64
#define STAGES 4

#define AROWB  160                      // A smem row bytes (32 fp32 + pad)
#define XROWB  80                       // X smem row bytes (32 fp16 + pad)
#define A_BYTES (MT * AROWB)            // 20480
#define X_BYTES (NC * XROWB)            // 5120
#define STAGE_BYTES (A_BYTES + X_BYTES) // 25600
#define SMEM_TOTAL  (STAGES * STAGE_BYTES) // 102400

#define ASCALE 256.0f
#define INV_ASCALE 0.00390625f

__device__ __align__(128) __half g_XT[NC * NNODES];            // 1 MB fp16
__device__ __align__(128) float g_part[SPLITS * NNODES * NC];  // 8 MB

// ---- helpers ----
__device__ __forceinline__ uint32_t smem_u32(const void* p) {
    uint32_t a;
    asm("{ .reg .u64 t; cvta.to.shared.u64 t, %1; cvt.u32.u64 %0, t; }" : "=r"(a) : "l"(p));
    return a;
}
__device__ __forceinline__ void cp_async16(uint32_t smem_dst, const void* gmem_src) {
    asm volatile("cp.async.cg.shared.global [%0], [%1], 16;" :: "r"(smem_dst), "l"(gmem_src));
}
#define CP_COMMIT() asm volatile("cp.async.commit_group;" ::: "memory")

// fp16x2 from two fp32, scaled by ASCALE
__device__ __forceinline__ uint32_t h2s(float lo, float hi) {
    __half2 v = __floats2half2_rn(lo * ASCALE, hi * ASCALE);
    return *(uint32_t*)&v;
}

// m16n8k16 fp16 x fp16 -> fp16 accumulate, C = 0 (fresh product each call)
__device__ __forceinline__ void mma_f16acc(uint32_t* d, const uint32_t* a, const uint32_t* b) {
    uint32_t z = 0;
    asm volatile(
        "mma.sync.aligned.m16n8k16.row.col.f16.f16.f16.f16 "
        "{%0,%1}, {%2,%3,%4,%5}, {%6,%7}, {%8,%9};"
        : "=r"(d[0]), "=r"(d[1])
        : "r"(a[0]), "r"(a[1]), "r"(a[2]), "r"(a[3]),
          "r"(b[0]), "r"(b[1]), "r"(z), "r"(z));
}

// ---------------- kernel 1: XT[b*16+d][m] = fp16(h[b][m*16+d]) ----------------
__global__ void __launch_bounds__(256) transpose_kernel(const float* __restrict__ h) {
    __shared__ float tile[16][130];
    int tid = threadIdx.x;
    int b  = blockIdx.x >> 6;
    int m0 = (blockIdx.x & 63) << 7;   // *128
    const float* src = h + (size_t)b * (NNODES * DDIM) + (size_t)m0 * DDIM;
#pragma unroll
    for (int i = 0; i < 8; i++) {
        int j = i * 256 + tid;                 // 2048 floats, coalesced
        tile[j & 15][j >> 4] = src[j];
    }
    __syncthreads();
#pragma unroll
    for (int i = 0; i < 4; i++) {
        int j = i * 256 + tid;                 // 1024 fp16x2 writes
        int d = j >> 6, mp = j & 63;
        __half2 v = __floats2half2_rn(tile[d][2 * mp], tile[d][2 * mp + 1]);
        *(__half2*)(g_XT + (size_t)(b * 16 + d) * NNODES + m0 + 2 * mp) = v;
    }
}

// ---------------- kernel 2: fp16-acc mma.sync GEMM -> g_part ----------------
// C[m][c] = sum_k A[m][k] * XT[c][k].  8 warps: wm=wid&3 (32 rows), wn=wid>>2 (32 cols).
__global__ void __launch_bounds__(256, 2) gemm_kernel(const float* __restrict__ A) {
    extern __shared__ char smem[];
    uint32_t sb = smem_u32(smem);

    int tid   = threadIdx.x;
    int n0    = blockIdx.x * MT;
    int split = blockIdx.y;
    int kbase = split * KRANGE;

    int lane = tid & 31, wid = tid >> 5;
    int wm = wid & 3, wn = wid >> 2;
    int qrow = lane >> 2, qcol = lane & 3;

    // cp.async coords: A = 1024 16B chunks (128 rows x 8), X = 256 chunks (64 rows x 4)
    uint32_t offA[4]; size_t gofA[4];
#pragma unroll
    for (int i = 0; i < 4; i++) {
        int q = i * 256 + tid;
        int row = q >> 3, c16 = q & 7;
        offA[i] = (uint32_t)(row * AROWB + c16 * 16);
        gofA[i] = (size_t)(n0 + row) * NNODES + (size_t)c16 * 4;   // fp32 elems
    }
    uint32_t offX; size_t gofX;
    {
        int row = tid >> 2, c16 = tid & 3;
        offX = (uint32_t)(row * XROWB + c16 * 16);
        gofX = (size_t)row * NNODES + (size_t)c16 * 8;             // fp16 elems
    }

    // prologue: tiles 0..2 -> slots 0..2
#pragma unroll
    for (int s = 0; s < STAGES - 1; s++) {
        int k0 = kbase + s * KT;
        uint32_t ab = sb + s * STAGE_BYTES;
#pragma unroll
        for (int i = 0; i < 4; i++) cp_async16(ab + offA[i], A + gofA[i] + k0);
        cp_async16(ab + A_BYTES + offX, g_XT + gofX + k0);
        CP_COMMIT();
    }

    float acc[2][4][4];
#pragma unroll
    for (int mf = 0; mf < 2; mf++)
#pragma unroll
        for (int nf = 0; nf < 4; nf++)
#pragma unroll
            for (int r = 0; r < 4; r++) acc[mf][nf][r] = 0.0f;

    const int arow0 = wm * 32 + qrow;
    const int xrow0 = wn * 32 + qrow;

    for (int it = 0; it < NIT; it++) {
        int slot = it & (STAGES - 1);
        asm volatile("cp.async.wait_group %0;" :: "n"(STAGES - 2) : "memory");
        __syncthreads();

        // refill freed slot first (hide latency)
        int nt = it + STAGES - 1;
        if (nt < NIT) {
            int k0 = kbase + nt * KT;
            uint32_t ab = sb + (nt & (STAGES - 1)) * STAGE_BYTES;
#pragma unroll
            for (int i = 0; i < 4; i++) cp_async16(ab + offA[i], A + gofA[i] + k0);
            cp_async16(ab + A_BYTES + offX, g_XT + gofX + k0);
        }
        CP_COMMIT();

        const float* As = (const float*)(smem + slot * STAGE_BYTES);
        const char*  Xs = smem + slot * STAGE_BYTES + A_BYTES;
#pragma unroll
        for (int kk = 0; kk < 2; kk++) {
            int kb = kk * 16;
            uint32_t a[2][4];
#pragma unroll
            for (int mf = 0; mf < 2; mf++) {
                int r = arow0 + mf * 16;
                float2 p0 = *(const float2*)(As + (size_t)r * 40 + kb + 2 * qcol);
                float2 p1 = *(const float2*)(As + (size_t)(r + 8) * 40 + kb + 2 * qcol);
                float2 p2 = *(const float2*)(As + (size_t)r * 40 + kb + 2 * qcol + 8);
                float2 p3 = *(const float2*)(As + (size_t)(r + 8) * 40 + kb + 2 * qcol + 8);
                a[mf][0] = h2s(p0.x, p0.y);
                a[mf][1] = h2s(p1.x, p1.y);
                a[mf][2] = h2s(p2.x, p2.y);
                a[mf][3] = h2s(p3.x, p3.y);
            }
            uint32_t b[4][2];
#pragma unroll
            for (int nf = 0; nf < 4; nf++) {
                int c = xrow0 + nf * 8;
                b[nf][0] = *(const uint32_t*)(Xs + c * XROWB + (kb + 2 * qcol) * 2);
                b[nf][1] = *(const uint32_t*)(Xs + c * XROWB + (kb + 2 * qcol) * 2 + 16);
            }
#pragma unroll
            for (int mf = 0; mf < 2; mf++)
#pragma unroll
                for (int nf = 0; nf < 4; nf++) {
                    uint32_t d[2];
                    mma_f16acc(d, a[mf], b[nf]);
                    float2 lo = __half22float2(*(__half2*)&d[0]);
                    float2 hi = __half22float2(*(__half2*)&d[1]);
                    acc[mf][nf][0] += lo.x;
                    acc[mf][nf][1] += lo.y;
                    acc[mf][nf][2] += hi.x;
                    acc[mf][nf][3] += hi.y;
                }
        }
    }
    asm volatile("cp.async.wait_group 0;" ::: "memory");

    // epilogue: undo the x256 A scale
#pragma unroll
    for (int mf = 0; mf < 2; mf++)
#pragma unroll
        for (int nf = 0; nf < 4; nf++) {
            int m = n0 + wm * 32 + mf * 16 + qrow;
            int c = wn * 32 + nf * 8 + qcol * 2;
            float* p0 = g_part + ((size_t)split * NNODES + m) * NC + c;
            *(float2*)p0 = make_float2(acc[mf][nf][0] * INV_ASCALE, acc[mf][nf][1] * INV_ASCALE);
            float* p1 = g_part + ((size_t)split * NNODES + m + 8) * NC + c;
            *(float2*)p1 = make_float2(acc[mf][nf][2] * INV_ASCALE, acc[mf][nf][3] * INV_ASCALE);
        }
}

// ---------------- kernel 3: fused MLPs ----------------
__global__ void __launch_bounds__(256) mlp_kernel(
    const float* __restrict__ h, const float* __restrict__ t,
    const float* __restrict__ W1f, const float* __restrict__ b1f,
    const float* __restrict__ W2f, const float* __restrict__ b2f,
    const float* __restrict__ W1g, const float* __restrict__ b1g,
    const float* __restrict__ W2g, const float* __restrict__ b2g,
    float* __restrict__ out) {
    __shared__ float sW1f[17 * 64], sW2f[64 * 16], sW1g[17 * 64], sW2g[64 * 16];
    __shared__ float sb1f[64], sb1g[64], sb2f[16], sb2g[16];
    int tid = threadIdx.x;
    for (int i = tid; i < 17 * 64; i += 256) { sW1f[i] = W1f[i]; sW1g[i] = W1g[i]; }
    for (int i = tid; i < 64 * 16; i += 256) { sW2f[i] = W2f[i]; sW2g[i] = W2g[i]; }
    if (tid < 64) { sb1f[tid] = b1f[tid]; sb1g[tid] = b1g[tid]; }
    if (tid < 16) { sb2f[tid] = b2f[tid]; sb2g[tid] = b2g[tid]; }
    __syncthreads();

    float tv = t[0];
    int gid = blockIdx.x * 256 + tid;
    int b = gid >> 13, n = gid & (NNODES - 1);

    float x[16], y[16];
    {
        size_t base = (size_t)n * NC + (size_t)b * DDIM;
        const float4* p0 = (const float4*)(g_part + base);
        const float4* p1 = (const float4*)(g_part + (size_t)1 * NNODES * NC + base);
        const float4* p2 = (const float4*)(g_part + (size_t)2 * NNODES * NC + base);
        const float4* p3 = (const float4*)(g_part + (size_t)3 * NNODES * NC + base);
#pragma unroll
        for (int k = 0; k < 4; k++) {
            float4 a = p0[k], bb = p1[k], c = p2[k], d = p3[k];
            x[4 * k + 0] = a.x + bb.x + c.x + d.x;
            x[4 * k + 1] = a.y + bb.y + c.y + d.y;
            x[4 * k + 2] = a.z + bb.z + c.z + d.z;
            x[4 * k + 3] = a.w + bb.w + c.w + d.w;
        }
        const float4* ph = (const float4*)(h + (size_t)b * NNODES * DDIM + (size_t)n * DDIM);
#pragma unroll
        for (int k = 0; k < 4; k++) {
            float4 a = ph[k];
            y[4 * k + 0] = a.x; y[4 * k + 1] = a.y; y[4 * k + 2] = a.z; y[4 * k + 3] = a.w;
        }
    }

    float drift[16], dacc[16];
#pragma unroll
    for (int d = 0; d < 16; d++) { drift[d] = sb2f[d]; dacc[d] = sb2g[d]; }

    for (int j = 0; j < 64; j++) {
        float zf = sb1f[j] + tv * sW1f[16 * 64 + j];
        float zg = sb1g[j] + tv * sW1g[16 * 64 + j];
#pragma unroll
        for (int i = 0; i < 16; i++) {
            zf = fmaf(x[i], sW1f[i * 64 + j], zf);
            zg = fmaf(y[i], sW1g[i * 64 + j], zg);
        }
        float af = 1.0f - 2.0f / (__expf(2.0f * zf) + 1.0f);   // tanh via MUFU exp
        float ag = 1.0f / (1.0f + __expf(-zg));
#pragma unroll
        for (int d = 0; d < 16; d++) {
            drift[d] = fmaf(af, sW2f[j * 16 + d], drift[d]);
            dacc[d]  = fmaf(ag, sW2g[j * 16 + d], dacc[d]);
        }
    }

    size_t o0 = (size_t)b * NNODES * DDIM + (size_t)n * DDIM;
    float4* od = (float4*)(out + o0);
    float4* og = (float4*)(out + (size_t)BATCH * NNODES * DDIM + o0);
#pragma unroll
    for (int k = 0; k < 4; k++) {
        od[k] = make_float4(drift[4 * k], drift[4 * k + 1], drift[4 * k + 2], drift[4 * k + 3]);
        float g0 = 0.1f / (1.0f + __expf(-dacc[4 * k + 0]));
        float g1 = 0.1f / (1.0f + __expf(-dacc[4 * k + 1]));
        float g2 = 0.1f / (1.0f + __expf(-dacc[4 * k + 2]));
        float g3 = 0.1f / (1.0f + __expf(-dacc[4 * k + 3]));
        og[k] = make_float4(g0, g1, g2, g3);
    }
}

extern "C" void kernel_launch(void* const* d_in, const int* in_sizes, int n_in,
                              void* d_out, int out_size) {
    (void)in_sizes; (void)n_in; (void)out_size;
    const float* h   = (const float*)d_in[0];
    const float* t   = (const float*)d_in[1];
    const float* A   = (const float*)d_in[2];
    const float* W1f = (const float*)d_in[3];
    const float* b1f = (const float*)d_in[4];
    const float* W2f = (const float*)d_in[5];
    const float* b2f = (const float*)d_in[6];
    const float* W1g = (const float*)d_in[7];
    const float* b1g = (const float*)d_in[8];
    const float* W2g = (const float*)d_in[9];
    const float* b2g = (const float*)d_in[10];
    float* out = (float*)d_out;

    cudaFuncSetAttribute(gemm_kernel, cudaFuncAttributeMaxDynamicSharedMemorySize, SMEM_TOTAL);

    transpose_kernel<<<256, 256>>>(h);
    gemm_kernel<<<dim3(NMT, SPLITS), 256, SMEM_TOTAL>>>(A);
    mlp_kernel<<<128, 256>>>(h, t, W1f, b1f, W2f, b2f, W1g, b1g, W2g, b2g, out);
}